// round 5
// baseline (speedup 1.0000x reference)
#include <cuda_runtime.h>
#include <math.h>

// Problem constants
#define Bn   16
#define Nn   16
#define Hh   896
#define Ww   896
#define Cc   3
#define PH   300
#define PW   300
#define MINPH 60.0f

#define NPIX (Hh*Ww)                         // 802816
#define IMG_ELEMS ((size_t)Bn*Hh*Ww*Cc)      // 38,535,168

// Output layout: imgs_out [B,H,W,C], pboxes [B,N,4], valid [B,N], td [B,N,3], grads [PH,PW,C]
#define OFF_PBOX  (IMG_ELEMS)
#define OFF_VALID (OFF_PBOX + (size_t)Bn*Nn*4)
#define OFF_TD    (OFF_VALID + (size_t)Bn*Nn)
#define OFF_GRADS (OFF_TD + (size_t)Bn*Nn*3)

// Scratch (__device__ globals)
__device__ int4   g_boxi[Bn*Nn];     // {yp, xp, ph, pw}; ph=pw=0 if invalid
__device__ float4 g_boxf[Bn*Nn];     // {inv_y, yp*inv_y+0.5, inv_x, xp*inv_x+0.5}
__device__ float  g_A[Bn*Nn*PH];     // row weight sums per box
__device__ float  g_Bw[Bn*Nn*PW];    // col weight sums per box

// ---------------------------------------------------------------------------
// Kernel 1: fused _create + separable VJP vectors. One block per (b,n).
// All threads compute the box params redundantly (no barrier, no serialization).
// ---------------------------------------------------------------------------
__global__ void __launch_bounds__(320) k_init(const float* __restrict__ boxes,
                                              const int*   __restrict__ td,
                                              float* __restrict__ out)
{
    const int bn = blockIdx.x;

    float ymin = __ldg(boxes + bn*4+0);
    float xmin = __ldg(boxes + bn*4+1);
    float ymax = __ldg(boxes + bn*4+2);
    float xmax = __ldg(boxes + bn*4+3);

    float h  = ymax - ymin;
    float w  = xmax - xmin;
    float pwf = h * 0.5f;
    float phf = pwf;
    float oy = ymin + h * 0.5f;
    float ox = xmin + w * 0.5f;
    float yp = fmaxf(oy - phf * 0.5f, 0.0f);
    float xp = fmaxf(ox - pwf * 0.5f, 0.0f);
    if (yp + phf > (float)Hh) yp = (float)Hh - phf;
    if (xp + pwf > (float)Ww) xp = (float)Ww - pwf;

    bool valid = (phf > MINPH);

    int4 bi; float4 bf;
    if (!valid) {
        bi = make_int4(0,0,0,0);
        bf = make_float4(0.f,0.f,0.f,0.f);
    } else {
        int ypi = (int)yp, xpi = (int)xp;
        int phi = max((int)phf, 1);
        int pwi = max((int)pwf, 1);
        bi = make_int4(ypi, xpi, phi, pwi);
        float s0 = (float)phi / (float)PH;  float inv0 = 1.0f / s0;
        float s1 = (float)pwi / (float)PW;  float inv1 = 1.0f / s1;
        bf = make_float4(inv0, (float)ypi*inv0 + 0.5f,
                         inv1, (float)xpi*inv1 + 0.5f);
    }

    if (threadIdx.x == 0) {
        float* out_pb = out + OFF_PBOX;
        out_pb[bn*4+0] = yp; out_pb[bn*4+1] = xp;
        out_pb[bn*4+2] = phf; out_pb[bn*4+3] = pwf;
        out[OFF_VALID + bn] = valid ? 1.0f : 0.0f;
        #pragma unroll
        for (int k = 0; k < 3; ++k)
            out[OFF_TD + (size_t)bn*3 + k] = (__ldg(td + bn*3+k) != 0) ? 1.0f : 0.0f;
        g_boxi[bn] = bi;
        g_boxf[bn] = bf;
    }

    int p = threadIdx.x;
    if (p >= PH) return;
    float a = 0.0f, bb = 0.0f;
    if (bi.z > 0) {
        {
            float r = (float)bi.z / (float)PH;
            int k0 = (int)floorf(((float)p + 0.5f) * r - 0.5f) - 2;
            #pragma unroll
            for (int dk = 0; dk < 5; ++dk) {
                int k = k0 + dk;
                if (k < 0 || k >= bi.z) continue;
                float u = ((float)k + 0.5f) * bf.x - 0.5f;
                float wgt = 1.0f - fabsf(u - (float)p);
                if (wgt > 0.0f) a += wgt;
            }
        }
        {
            float r = (float)bi.w / (float)PW;
            int k0 = (int)floorf(((float)p + 0.5f) * r - 0.5f) - 2;
            #pragma unroll
            for (int dk = 0; dk < 5; ++dk) {
                int k = k0 + dk;
                if (k < 0 || k >= bi.w) continue;
                float u = ((float)k + 0.5f) * bf.z - 0.5f;
                float wgt = 1.0f - fabsf(u - (float)p);
                if (wgt > 0.0f) bb += wgt;
            }
        }
    }
    g_A [bn*PH + p] = a;
    g_Bw[bn*PW + p] = bb;
}

// ---------------------------------------------------------------------------
// Kernel 2: copy pass. Pure streaming; skips float4s whose spanned pixels are
// all box-covered (the paint pass will write those). No patch access at all.
// One warp per (row, 128-px segment); lane l owns float4 l, l+32, l+64.
// ---------------------------------------------------------------------------
__global__ void __launch_bounds__(256) k_copy(const float* __restrict__ images,
                                              float* __restrict__ out)
{
    const int b    = blockIdx.z;
    const int j0   = blockIdx.x * 128;
    const int i    = blockIdx.y * 8 + (threadIdx.x >> 5);
    const int lane = threadIdx.x & 31;

    __shared__ int4 sbi[Nn];
    if (threadIdx.x < Nn)
        sbi[threadIdx.x] = g_boxi[b*Nn + threadIdx.x];
    __syncthreads();

    bool inter = false;
    if (lane < Nn) {
        int4 bx = sbi[lane];
        inter = (bx.z > 0) &&
                ((unsigned)(i - bx.x) < (unsigned)bx.z) &&   // row containment
                (bx.y < j0 + 128) && (bx.y + bx.w > j0);     // col overlap
    }
    unsigned mask = __ballot_sync(0xffffffffu, inter);

    size_t fbase = ((size_t)b * NPIX + (size_t)i * Ww + j0) * 3;  // 16B aligned
    const float4* src4 = (const float4*)(images + fbase);
    float4*       dst4 = (float4*)(out + fbase);

    if (mask == 0u) {
        dst4[lane     ] = src4[lane     ];
        dst4[lane + 32] = src4[lane + 32];
        dst4[lane + 64] = src4[lane + 64];
        return;
    }

    #pragma unroll
    for (int r = 0; r < 3; ++r) {
        int l4 = lane + r*32;
        int f0 = l4 * 4;
        int ja = j0 + f0 / 3;          // first pixel spanned by this float4
        int jb = j0 + (f0 + 3) / 3;    // second pixel spanned

        bool covA = false, covB = false;
        unsigned m = mask;
        while (m) {
            int n = __ffs(m) - 1;
            int4 bx = sbi[n];
            covA |= (unsigned)(ja - bx.y) < (unsigned)bx.w;
            covB |= (unsigned)(jb - bx.y) < (unsigned)bx.w;
            if (covA && covB) break;
            m &= m - 1;
        }
        if (!(covA && covB))
            dst4[l4] = src4[l4];       // covered float4s are paint's job
    }
}

// ---------------------------------------------------------------------------
// Kernel 3: paint pass. One block-tile (4 rows x 64 cols) of box (b,n)'s rect.
// Pixel painted iff inside box n AND not inside any higher box m>n (same b).
// Patch reads are monotone across a warp -> L1-friendly; writes contiguous.
// ---------------------------------------------------------------------------
#define PT_W 64
#define PT_H 4
__global__ void __launch_bounds__(256) k_paint(const float* __restrict__ patch,
                                               float* __restrict__ out)
{
    const int bn = blockIdx.z;           // b*Nn + n
    const int b  = bn >> 4;
    const int n  = bn & 15;

    __shared__ int4   sbi[Nn];
    __shared__ float4 sbf;
    if (threadIdx.x < Nn)
        sbi[threadIdx.x] = g_boxi[b*Nn + threadIdx.x];
    if (threadIdx.x == 32)
        sbf = g_boxf[bn];
    __syncthreads();

    const int4 me = sbi[n];
    if (me.z == 0) return;

    const int ly = blockIdx.y * PT_H + (threadIdx.x >> 6);
    const int lx = blockIdx.x * PT_W + (threadIdx.x & 63);
    if (ly >= me.z || lx >= me.w) return;

    const int i = me.x + ly;
    const int j = me.y + lx;

    // occluded by a higher box?
    for (int m = n + 1; m < Nn; ++m) {
        int4 bx = sbi[m];
        if ((unsigned)(i - bx.x) < (unsigned)bx.z &&
            (unsigned)(j - bx.y) < (unsigned)bx.w) return;
    }

    // bilinear sample (interior: scale < 1 always)
    float4 f = sbf;
    float u  = ((float)i + 0.5f) * f.x - f.y;
    float vv = ((float)j + 0.5f) * f.z - f.w;
    float fu = floorf(u), fv = floorf(vv);
    float du = u - fu,    dv = vv - fv;
    int r0 = (int)fu, c0 = (int)fv;
    const float* p00 = patch + ((size_t)r0 * PW + c0) * 3;
    float w00 = (1.0f-du)*(1.0f-dv);
    float w01 = (1.0f-du)*dv;
    float w10 = du*(1.0f-dv);
    float w11 = du*dv;

    float* o = out + ((size_t)b * NPIX + (size_t)i * Ww + j) * 3;
    #pragma unroll
    for (int c = 0; c < 3; ++c)
        o[c] = w00*p00[c] + w01*p00[3+c] + w10*p00[PW*3+c] + w11*p00[PW*3+3+c];
}

// ---------------------------------------------------------------------------
// Kernel 4: grads[p,q,c] = sum_b (sum_n A_bn[p]*B_bn[q]) * hg[b,p,q,c]
// ---------------------------------------------------------------------------
__global__ void __launch_bounds__(256) k_grads(const float* __restrict__ hg,
                                               float* __restrict__ outg)
{
    const int base = blockIdx.x * 256;
    const int idx  = base + threadIdx.x;     // p*PW + q
    const int p0   = base / PW;

    __shared__ float As[2][Bn*Nn];
    {
        int t = threadIdx.x;                  // 256 == Bn*Nn
        As[0][t] = g_A[t*PH + p0];
        As[1][t] = (p0 + 1 < PH) ? g_A[t*PH + p0 + 1] : 0.0f;
    }
    __syncthreads();
    if (idx >= PH*PW) return;

    const int p = idx / PW;
    const int q = idx - p * PW;
    const float* Arow = As[p - p0];

    float o0 = 0.f, o1 = 0.f, o2 = 0.f;
    #pragma unroll 4
    for (int b = 0; b < Bn; ++b) {
        float s = 0.f;
        #pragma unroll
        for (int n = 0; n < Nn; ++n)
            s += Arow[b*Nn + n] * g_Bw[(b*Nn + n)*PW + q];
        size_t hb = ((size_t)b * PH * PW + idx) * 3;
        o0 += s * hg[hb+0];
        o1 += s * hg[hb+1];
        o2 += s * hg[hb+2];
    }
    size_t gb = (size_t)idx * 3;
    outg[gb+0] = o0;
    outg[gb+1] = o1;
    outg[gb+2] = o2;
}

// ---------------------------------------------------------------------------
extern "C" void kernel_launch(void* const* d_in, const int* in_sizes, int n_in,
                              void* d_out, int out_size)
{
    const float* boxes  = (const float*)d_in[0];
    const float* images = (const float*)d_in[1];
    const float* patch  = (const float*)d_in[2];
    const float* hg     = (const float*)d_in[3];
    const int*   td     = (const int*)  d_in[4];
    float* out = (float*)d_out;

    k_init<<<Bn*Nn, 320>>>(boxes, td, out);
    k_copy<<<dim3(Ww/128, Hh/8, Bn), 256>>>(images, out);
    // max patch box side = 260 px -> 5 x-tiles of 64, 65 y-tiles of 4
    k_paint<<<dim3(5, 65, Bn*Nn), 256>>>(patch, out);
    k_grads<<<(PH*PW + 255)/256, 256>>>(hg, out + OFF_GRADS);
}

// round 6
// speedup vs baseline: 1.3001x; 1.3001x over previous
#include <cuda_runtime.h>
#include <math.h>

// Problem constants
#define Bn   16
#define Nn   16
#define Hh   896
#define Ww   896
#define Cc   3
#define PH   300
#define PW   300
#define MINPH 60.0f

#define NPIX (Hh*Ww)                         // 802816
#define IMG_ELEMS ((size_t)Bn*Hh*Ww*Cc)      // 38,535,168

// Output layout: imgs_out [B,H,W,C], pboxes [B,N,4], valid [B,N], td [B,N,3], grads [PH,PW,C]
#define OFF_PBOX  (IMG_ELEMS)
#define OFF_VALID (OFF_PBOX + (size_t)Bn*Nn*4)
#define OFF_TD    (OFF_VALID + (size_t)Bn*Nn)
#define OFF_GRADS (OFF_TD + (size_t)Bn*Nn*3)

// Scratch (__device__ globals)
__device__ int4   g_boxi[Bn*Nn];     // {yp, xp, ph, pw}; ph=pw=0 if invalid
__device__ float4 g_boxf[Bn*Nn];     // {inv_y, yp*inv_y+0.5, inv_x, xp*inv_x+0.5}
__device__ float  g_A[Bn*Nn*PH];     // row weight sums per box
__device__ float  g_Bw[Bn*Nn*PW];    // col weight sums per box

// ---------------------------------------------------------------------------
// Kernel 1: fused _create + separable VJP vectors. One block per (b,n).
// All threads compute box params redundantly (no barrier before A/B work).
// ---------------------------------------------------------------------------
__global__ void __launch_bounds__(320) k_init(const float* __restrict__ boxes,
                                              const int*   __restrict__ td,
                                              float* __restrict__ out)
{
    const int bn = blockIdx.x;

    float ymin = __ldg(boxes + bn*4+0);
    float xmin = __ldg(boxes + bn*4+1);
    float ymax = __ldg(boxes + bn*4+2);
    float xmax = __ldg(boxes + bn*4+3);

    float h  = ymax - ymin;
    float w  = xmax - xmin;
    float pwf = h * 0.5f;
    float phf = pwf;
    float oy = ymin + h * 0.5f;
    float ox = xmin + w * 0.5f;
    float yp = fmaxf(oy - phf * 0.5f, 0.0f);
    float xp = fmaxf(ox - pwf * 0.5f, 0.0f);
    if (yp + phf > (float)Hh) yp = (float)Hh - phf;
    if (xp + pwf > (float)Ww) xp = (float)Ww - pwf;

    bool valid = (phf > MINPH);

    int4 bi; float4 bf;
    if (!valid) {
        bi = make_int4(0,0,0,0);
        bf = make_float4(0.f,0.f,0.f,0.f);
    } else {
        int ypi = (int)yp, xpi = (int)xp;
        int phi = max((int)phf, 1);
        int pwi = max((int)pwf, 1);
        bi = make_int4(ypi, xpi, phi, pwi);
        float s0 = (float)phi / (float)PH;  float inv0 = 1.0f / s0;
        float s1 = (float)pwi / (float)PW;  float inv1 = 1.0f / s1;
        bf = make_float4(inv0, (float)ypi*inv0 + 0.5f,
                         inv1, (float)xpi*inv1 + 0.5f);
    }

    if (threadIdx.x == 0) {
        float* out_pb = out + OFF_PBOX;
        out_pb[bn*4+0] = yp; out_pb[bn*4+1] = xp;
        out_pb[bn*4+2] = phf; out_pb[bn*4+3] = pwf;
        out[OFF_VALID + bn] = valid ? 1.0f : 0.0f;
        #pragma unroll
        for (int k = 0; k < 3; ++k)
            out[OFF_TD + (size_t)bn*3 + k] = (__ldg(td + bn*3+k) != 0) ? 1.0f : 0.0f;
        g_boxi[bn] = bi;
        g_boxf[bn] = bf;
    }

    int p = threadIdx.x;
    if (p >= PH) return;
    float a = 0.0f, bb = 0.0f;
    if (bi.z > 0) {
        {
            float r = (float)bi.z / (float)PH;
            int k0 = (int)floorf(((float)p + 0.5f) * r - 0.5f) - 2;
            #pragma unroll
            for (int dk = 0; dk < 5; ++dk) {
                int k = k0 + dk;
                if (k < 0 || k >= bi.z) continue;
                float u = ((float)k + 0.5f) * bf.x - 0.5f;
                float wgt = 1.0f - fabsf(u - (float)p);
                if (wgt > 0.0f) a += wgt;
            }
        }
        {
            float r = (float)bi.w / (float)PW;
            int k0 = (int)floorf(((float)p + 0.5f) * r - 0.5f) - 2;
            #pragma unroll
            for (int dk = 0; dk < 5; ++dk) {
                int k = k0 + dk;
                if (k < 0 || k >= bi.w) continue;
                float u = ((float)k + 0.5f) * bf.z - 0.5f;
                float wgt = 1.0f - fabsf(u - (float)p);
                if (wgt > 0.0f) bb += wgt;
            }
        }
    }
    g_A [bn*PH + p] = a;
    g_Bw[bn*PW + p] = bb;
}

// ---------------------------------------------------------------------------
// Bilinear sample of patch (3 channels) at image pixel (fi, jj) under box f.
// ---------------------------------------------------------------------------
__device__ __forceinline__ void bil3(float4 f, float fi, int jj,
                                     const float* __restrict__ patch, float* o)
{
    float u  = fi * f.x - f.y;
    float vv = ((float)jj + 0.5f) * f.z - f.w;
    float fu = floorf(u), fv = floorf(vv);
    float du = u - fu,    dv = vv - fv;
    int r0 = (int)fu, c0 = (int)fv;
    const float* p00 = patch + ((size_t)r0 * PW + c0) * 3;
    float w00 = (1.0f-du)*(1.0f-dv);
    float w01 = (1.0f-du)*dv;
    float w10 = du*(1.0f-dv);
    float w11 = du*dv;
    #pragma unroll
    for (int c = 0; c < 3; ++c)
        o[c] = w00*p00[c] + w01*p00[3+c] + w10*p00[PW*3+c] + w11*p00[PW*3+3+c];
}

// ---------------------------------------------------------------------------
// Kernel 2: image composite (R4-proven). One warp per 128-px row segment;
// lane l owns float4 l, l+32, l+64 (fully coalesced). Warp-level box mask
// (row containment baked in). Each float4 spans 2 pixels; src read skipped
// when both are box-covered.
// ---------------------------------------------------------------------------
__global__ void __launch_bounds__(256) k_image(const float* __restrict__ images,
                                               const float* __restrict__ patch,
                                               float* __restrict__ out)
{
    const int b    = blockIdx.z;
    const int j0   = blockIdx.x * 128;
    const int i    = blockIdx.y * 8 + (threadIdx.x >> 5);
    const int lane = threadIdx.x & 31;

    __shared__ int4   sbi[Nn];
    __shared__ float4 sbf[Nn];
    if (threadIdx.x < Nn) {
        sbi[threadIdx.x] = g_boxi[b*Nn + threadIdx.x];
        sbf[threadIdx.x] = g_boxf[b*Nn + threadIdx.x];
    }
    __syncthreads();

    bool inter = false;
    if (lane < Nn) {
        int4 bx = sbi[lane];
        inter = (bx.z > 0) &&
                ((unsigned)(i - bx.x) < (unsigned)bx.z) &&
                (bx.y < j0 + 128) && (bx.y + bx.w > j0);
    }
    unsigned mask = __ballot_sync(0xffffffffu, inter);

    size_t fbase = ((size_t)b * NPIX + (size_t)i * Ww + j0) * 3;
    const float4* src4 = (const float4*)(images + fbase);
    float4*       dst4 = (float4*)(out + fbase);

    if (mask == 0u) {
        dst4[lane     ] = src4[lane     ];
        dst4[lane + 32] = src4[lane + 32];
        dst4[lane + 64] = src4[lane + 64];
        return;
    }

    const float fi = (float)i + 0.5f;

    #pragma unroll
    for (int r = 0; r < 3; ++r) {
        int l4 = lane + r*32;
        int f0 = l4 * 4;
        int pa = f0 / 3;
        int pb = (f0 + 3) / 3;

        int hitA = -1, hitB = -1;
        {
            int ja = j0 + pa, jb = j0 + pb;
            unsigned m = mask;
            while (m) {
                int n = 31 - __clz(m);
                int4 bx = sbi[n];
                if (hitA < 0 && (unsigned)(ja - bx.y) < (unsigned)bx.w) hitA = n;
                if (hitB < 0 && (unsigned)(jb - bx.y) < (unsigned)bx.w) hitB = n;
                if (hitA >= 0 && hitB >= 0) break;
                m &= ~(1u << n);
            }
        }

        float va[3], vb[3];
        if (hitA >= 0) bil3(sbf[hitA], fi, j0 + pa, patch, va);
        if (hitB >= 0) bil3(sbf[hitB], fi, j0 + pb, patch, vb);

        float4 v = make_float4(0.f, 0.f, 0.f, 0.f);
        if (hitA < 0 || hitB < 0)
            v = src4[l4];

        float ov[4] = { v.x, v.y, v.z, v.w };
        #pragma unroll
        for (int e = 0; e < 4; ++e) {
            int fidx = f0 + e;
            int p = fidx / 3;
            int c = fidx - p * 3;
            if (p == pa) { if (hitA >= 0) ov[e] = va[c]; }
            else         { if (hitB >= 0) ov[e] = vb[c]; }
        }
        dst4[l4] = make_float4(ov[0], ov[1], ov[2], ov[3]);
    }
}

// ---------------------------------------------------------------------------
// Kernel 3: grads with 4-way b-split. 4 lanes (aligned quad) per output cell;
// lane sub handles images {sub, sub+4, sub+8, sub+12}; shfl_xor reduction.
// Block covers 64 cells (256 threads). 1407 blocks -> 4x the warps of R4.
// ---------------------------------------------------------------------------
__global__ void __launch_bounds__(256) k_grads(const float* __restrict__ hg,
                                               float* __restrict__ outg)
{
    const int cell0 = blockIdx.x * 64;
    const int cell  = cell0 + (threadIdx.x >> 2);   // p*PW + q
    const int sub   = threadIdx.x & 3;
    const int p0    = cell0 / PW;

    __shared__ float As[2][Bn*Nn];
    {
        int t = threadIdx.x;                         // 256 == Bn*Nn
        As[0][t] = g_A[t*PH + p0];
        As[1][t] = (p0 + 1 < PH) ? g_A[t*PH + p0 + 1] : 0.0f;
    }
    __syncthreads();
    if (cell >= PH*PW) return;

    const int p = cell / PW;
    const int q = cell - p * PW;
    const float* Arow = As[p - p0];

    float o0 = 0.f, o1 = 0.f, o2 = 0.f;
    #pragma unroll
    for (int bb = 0; bb < 4; ++bb) {
        const int b = sub + bb*4;
        float s = 0.f;
        #pragma unroll
        for (int n = 0; n < Nn; ++n)
            s += Arow[b*Nn + n] * __ldg(g_Bw + (b*Nn + n)*PW + q);
        size_t hb = ((size_t)b * PH * PW + cell) * 3;
        o0 += s * __ldg(hg + hb + 0);
        o1 += s * __ldg(hg + hb + 1);
        o2 += s * __ldg(hg + hb + 2);
    }

    o0 += __shfl_xor_sync(0xffffffffu, o0, 1);
    o1 += __shfl_xor_sync(0xffffffffu, o1, 1);
    o2 += __shfl_xor_sync(0xffffffffu, o2, 1);
    o0 += __shfl_xor_sync(0xffffffffu, o0, 2);
    o1 += __shfl_xor_sync(0xffffffffu, o1, 2);
    o2 += __shfl_xor_sync(0xffffffffu, o2, 2);

    if (sub == 0) {
        size_t gb = (size_t)cell * 3;
        outg[gb+0] = o0;
        outg[gb+1] = o1;
        outg[gb+2] = o2;
    }
}

// ---------------------------------------------------------------------------
extern "C" void kernel_launch(void* const* d_in, const int* in_sizes, int n_in,
                              void* d_out, int out_size)
{
    const float* boxes  = (const float*)d_in[0];
    const float* images = (const float*)d_in[1];
    const float* patch  = (const float*)d_in[2];
    const float* hg     = (const float*)d_in[3];
    const int*   td     = (const int*)  d_in[4];
    float* out = (float*)d_out;

    k_init<<<Bn*Nn, 320>>>(boxes, td, out);
    k_image<<<dim3(Ww/128, Hh/8, Bn), 256>>>(images, patch, out);
    k_grads<<<(PH*PW*4 + 255)/256, 256>>>(hg, out + OFF_GRADS);
}

// round 7
// speedup vs baseline: 1.3251x; 1.0192x over previous
#include <cuda_runtime.h>
#include <math.h>

// Problem constants
#define Bn   16
#define Nn   16
#define Hh   896
#define Ww   896
#define Cc   3
#define PH   300
#define PW   300
#define MINPH 60.0f

#define NPIX  (Hh*Ww)                        // 802816
#define NCELL (PH*PW)                        // 90000
#define IMG_ELEMS ((size_t)Bn*Hh*Ww*Cc)      // 38,535,168

// Output layout: imgs_out [B,H,W,C], pboxes [B,N,4], valid [B,N], td [B,N,3], grads [PH,PW,C]
#define OFF_PBOX  (IMG_ELEMS)
#define OFF_VALID (OFF_PBOX + (size_t)Bn*Nn*4)
#define OFF_TD    (OFF_VALID + (size_t)Bn*Nn)
#define OFF_GRADS (OFF_TD + (size_t)Bn*Nn*3)

// Scratch (__device__ globals)
__device__ int4   g_boxi[Bn*Nn];        // {yp, xp, ph, pw}; ph=pw=0 if invalid
__device__ float4 g_boxf[Bn*Nn];        // {inv_y, yp*inv_y+0.5, inv_x, xp*inv_x+0.5}
__device__ float  g_A[Bn*Nn*PH];        // row weight sums per box
__device__ float  g_Bw[Bn*Nn*PW];       // col weight sums per box
__device__ float  g_S[(size_t)Bn*NCELL];// per-image rank-16 weight field (5.76 MB)

// ---------------------------------------------------------------------------
// Kernel 1: fused _create + separable VJP vectors. One block per (b,n).
// ---------------------------------------------------------------------------
__global__ void __launch_bounds__(320) k_init(const float* __restrict__ boxes,
                                              const int*   __restrict__ td,
                                              float* __restrict__ out)
{
    const int bn = blockIdx.x;

    float ymin = __ldg(boxes + bn*4+0);
    float xmin = __ldg(boxes + bn*4+1);
    float ymax = __ldg(boxes + bn*4+2);
    float xmax = __ldg(boxes + bn*4+3);

    float h  = ymax - ymin;
    float w  = xmax - xmin;
    float pwf = h * 0.5f;
    float phf = pwf;
    float oy = ymin + h * 0.5f;
    float ox = xmin + w * 0.5f;
    float yp = fmaxf(oy - phf * 0.5f, 0.0f);
    float xp = fmaxf(ox - pwf * 0.5f, 0.0f);
    if (yp + phf > (float)Hh) yp = (float)Hh - phf;
    if (xp + pwf > (float)Ww) xp = (float)Ww - pwf;

    bool valid = (phf > MINPH);

    int4 bi; float4 bf;
    if (!valid) {
        bi = make_int4(0,0,0,0);
        bf = make_float4(0.f,0.f,0.f,0.f);
    } else {
        int ypi = (int)yp, xpi = (int)xp;
        int phi = max((int)phf, 1);
        int pwi = max((int)pwf, 1);
        bi = make_int4(ypi, xpi, phi, pwi);
        float s0 = (float)phi / (float)PH;  float inv0 = 1.0f / s0;
        float s1 = (float)pwi / (float)PW;  float inv1 = 1.0f / s1;
        bf = make_float4(inv0, (float)ypi*inv0 + 0.5f,
                         inv1, (float)xpi*inv1 + 0.5f);
    }

    if (threadIdx.x == 0) {
        float* out_pb = out + OFF_PBOX;
        out_pb[bn*4+0] = yp; out_pb[bn*4+1] = xp;
        out_pb[bn*4+2] = phf; out_pb[bn*4+3] = pwf;
        out[OFF_VALID + bn] = valid ? 1.0f : 0.0f;
        #pragma unroll
        for (int k = 0; k < 3; ++k)
            out[OFF_TD + (size_t)bn*3 + k] = (__ldg(td + bn*3+k) != 0) ? 1.0f : 0.0f;
        g_boxi[bn] = bi;
        g_boxf[bn] = bf;
    }

    int p = threadIdx.x;
    if (p >= PH) return;
    float a = 0.0f, bb = 0.0f;
    if (bi.z > 0) {
        {
            float r = (float)bi.z / (float)PH;
            int k0 = (int)floorf(((float)p + 0.5f) * r - 0.5f) - 2;
            #pragma unroll
            for (int dk = 0; dk < 5; ++dk) {
                int k = k0 + dk;
                if (k < 0 || k >= bi.z) continue;
                float u = ((float)k + 0.5f) * bf.x - 0.5f;
                float wgt = 1.0f - fabsf(u - (float)p);
                if (wgt > 0.0f) a += wgt;
            }
        }
        {
            float r = (float)bi.w / (float)PW;
            int k0 = (int)floorf(((float)p + 0.5f) * r - 0.5f) - 2;
            #pragma unroll
            for (int dk = 0; dk < 5; ++dk) {
                int k = k0 + dk;
                if (k < 0 || k >= bi.w) continue;
                float u = ((float)k + 0.5f) * bf.z - 0.5f;
                float wgt = 1.0f - fabsf(u - (float)p);
                if (wgt > 0.0f) bb += wgt;
            }
        }
    }
    g_A [bn*PH + p] = a;
    g_Bw[bn*PW + p] = bb;
}

// ---------------------------------------------------------------------------
// Bilinear sample of patch (3 channels) at image pixel (fi, jj) under box f.
// ---------------------------------------------------------------------------
__device__ __forceinline__ void bil3(float4 f, float fi, int jj,
                                     const float* __restrict__ patch, float* o)
{
    float u  = fi * f.x - f.y;
    float vv = ((float)jj + 0.5f) * f.z - f.w;
    float fu = floorf(u), fv = floorf(vv);
    float du = u - fu,    dv = vv - fv;
    int r0 = (int)fu, c0 = (int)fv;
    const float* p00 = patch + ((size_t)r0 * PW + c0) * 3;
    float w00 = (1.0f-du)*(1.0f-dv);
    float w01 = (1.0f-du)*dv;
    float w10 = du*(1.0f-dv);
    float w11 = du*dv;
    #pragma unroll
    for (int c = 0; c < 3; ++c)
        o[c] = w00*p00[c] + w01*p00[3+c] + w10*p00[PW*3+c] + w11*p00[PW*3+3+c];
}

// ---------------------------------------------------------------------------
// Kernel 2: image composite (R4-proven) + streaming stores on output.
// ---------------------------------------------------------------------------
__global__ void __launch_bounds__(256) k_image(const float* __restrict__ images,
                                               const float* __restrict__ patch,
                                               float* __restrict__ out)
{
    const int b    = blockIdx.z;
    const int j0   = blockIdx.x * 128;
    const int i    = blockIdx.y * 8 + (threadIdx.x >> 5);
    const int lane = threadIdx.x & 31;

    __shared__ int4   sbi[Nn];
    __shared__ float4 sbf[Nn];
    if (threadIdx.x < Nn) {
        sbi[threadIdx.x] = g_boxi[b*Nn + threadIdx.x];
        sbf[threadIdx.x] = g_boxf[b*Nn + threadIdx.x];
    }
    __syncthreads();

    bool inter = false;
    if (lane < Nn) {
        int4 bx = sbi[lane];
        inter = (bx.z > 0) &&
                ((unsigned)(i - bx.x) < (unsigned)bx.z) &&
                (bx.y < j0 + 128) && (bx.y + bx.w > j0);
    }
    unsigned mask = __ballot_sync(0xffffffffu, inter);

    size_t fbase = ((size_t)b * NPIX + (size_t)i * Ww + j0) * 3;
    const float4* src4 = (const float4*)(images + fbase);
    float4*       dst4 = (float4*)(out + fbase);

    if (mask == 0u) {
        __stcs(dst4 + lane,      __ldcs(src4 + lane));
        __stcs(dst4 + lane + 32, __ldcs(src4 + lane + 32));
        __stcs(dst4 + lane + 64, __ldcs(src4 + lane + 64));
        return;
    }

    const float fi = (float)i + 0.5f;

    #pragma unroll
    for (int r = 0; r < 3; ++r) {
        int l4 = lane + r*32;
        int f0 = l4 * 4;
        int pa = f0 / 3;
        int pb = (f0 + 3) / 3;

        int hitA = -1, hitB = -1;
        {
            int ja = j0 + pa, jb = j0 + pb;
            unsigned m = mask;
            while (m) {
                int n = 31 - __clz(m);
                int4 bx = sbi[n];
                if (hitA < 0 && (unsigned)(ja - bx.y) < (unsigned)bx.w) hitA = n;
                if (hitB < 0 && (unsigned)(jb - bx.y) < (unsigned)bx.w) hitB = n;
                if (hitA >= 0 && hitB >= 0) break;
                m &= ~(1u << n);
            }
        }

        float va[3], vb[3];
        if (hitA >= 0) bil3(sbf[hitA], fi, j0 + pa, patch, va);
        if (hitB >= 0) bil3(sbf[hitB], fi, j0 + pb, patch, vb);

        float4 v = make_float4(0.f, 0.f, 0.f, 0.f);
        if (hitA < 0 || hitB < 0)
            v = __ldcs(src4 + l4);

        float ov[4] = { v.x, v.y, v.z, v.w };
        #pragma unroll
        for (int e = 0; e < 4; ++e) {
            int fidx = f0 + e;
            int p = fidx / 3;
            int c = fidx - p * 3;
            if (p == pa) { if (hitA >= 0) ov[e] = va[c]; }
            else         { if (hitB >= 0) ov[e] = vb[c]; }
        }
        __stcs(dst4 + l4, make_float4(ov[0], ov[1], ov[2], ov[3]));
    }
}

// ---------------------------------------------------------------------------
// Kernel 3: S[b][p][q] = sum_n A_bn[p] * B_bn[q]  (rank-16 outer product)
// grid = (10 p-chunks, b). A_b staged in smem; B_bn[q] in registers.
// ---------------------------------------------------------------------------
#define PCHUNK 30
__global__ void __launch_bounds__(320) k_s()
{
    const int b  = blockIdx.y;
    const int p0 = blockIdx.x * PCHUNK;
    const int q  = threadIdx.x;

    __shared__ float As[Nn][PH];
    for (int idx = threadIdx.x; idx < Nn*PH; idx += 320) {
        int n = idx / PH, p = idx - n * PH;
        As[n][p] = g_A[(b*Nn + n)*PH + p];
    }
    __syncthreads();
    if (q >= PW) return;

    float Br[Nn];
    #pragma unroll
    for (int n = 0; n < Nn; ++n)
        Br[n] = g_Bw[(b*Nn + n)*PW + q];

    #pragma unroll
    for (int dp = 0; dp < PCHUNK; ++dp) {
        int p = p0 + dp;
        float s = 0.0f;
        #pragma unroll
        for (int n = 0; n < Nn; ++n)
            s += As[n][p] * Br[n];
        g_S[((size_t)b*PH + p)*PW + q] = s;
    }
}

// ---------------------------------------------------------------------------
// Kernel 4: grads[cell,c] = sum_b S[b,cell] * hg[b,cell,c].
// float4-granular: each thread owns 4 consecutive cells -> per-b loads are
// 1x float4 (S) + 3x float4 (hg), all 16B-aligned. 4x bytes-in-flight vs R3.
// ---------------------------------------------------------------------------
__global__ void __launch_bounds__(256) k_g(const float* __restrict__ hg,
                                           float* __restrict__ outg)
{
    const int t     = blockIdx.x * 256 + threadIdx.x;
    const int cell0 = t * 4;
    if (cell0 >= NCELL) return;

    float o[12];
    #pragma unroll
    for (int j = 0; j < 12; ++j) o[j] = 0.0f;

    #pragma unroll 4
    for (int b = 0; b < Bn; ++b) {
        const float4 s4 = *(const float4*)(g_S + (size_t)b*NCELL + cell0);
        const float4* h4 = (const float4*)(hg + ((size_t)b*NCELL + cell0)*3);
        float4 h0 = __ldcs(h4 + 0);
        float4 h1 = __ldcs(h4 + 1);
        float4 h2 = __ldcs(h4 + 2);
        float s[4]  = { s4.x, s4.y, s4.z, s4.w };
        float hh[12] = { h0.x,h0.y,h0.z,h0.w, h1.x,h1.y,h1.z,h1.w,
                         h2.x,h2.y,h2.z,h2.w };
        #pragma unroll
        for (int j = 0; j < 12; ++j)
            o[j] += s[j/3] * hh[j];
    }

    float4* o4 = (float4*)(outg + (size_t)cell0 * 3);
    __stcs(o4 + 0, make_float4(o[0], o[1], o[2],  o[3]));
    __stcs(o4 + 1, make_float4(o[4], o[5], o[6],  o[7]));
    __stcs(o4 + 2, make_float4(o[8], o[9], o[10], o[11]));
}

// ---------------------------------------------------------------------------
extern "C" void kernel_launch(void* const* d_in, const int* in_sizes, int n_in,
                              void* d_out, int out_size)
{
    const float* boxes  = (const float*)d_in[0];
    const float* images = (const float*)d_in[1];
    const float* patch  = (const float*)d_in[2];
    const float* hg     = (const float*)d_in[3];
    const int*   td     = (const int*)  d_in[4];
    float* out = (float*)d_out;

    k_init<<<Bn*Nn, 320>>>(boxes, td, out);
    k_s<<<dim3(PH/PCHUNK, Bn), 320>>>();
    k_image<<<dim3(Ww/128, Hh/8, Bn), 256>>>(images, patch, out);
    k_g<<<(NCELL/4 + 255)/256, 256>>>(hg, out + OFF_GRADS);
}

// round 8
// speedup vs baseline: 1.3558x; 1.0232x over previous
#include <cuda_runtime.h>
#include <math.h>

// Problem constants
#define Bn   16
#define Nn   16
#define Hh   896
#define Ww   896
#define Cc   3
#define PH   300
#define PW   300
#define MINPH 60.0f

#define NPIX  (Hh*Ww)                        // 802816
#define NCELL (PH*PW)                        // 90000
#define IMG_ELEMS ((size_t)Bn*Hh*Ww*Cc)      // 38,535,168

// Output layout: imgs_out [B,H,W,C], pboxes [B,N,4], valid [B,N], td [B,N,3], grads [PH,PW,C]
#define OFF_PBOX  (IMG_ELEMS)
#define OFF_VALID (OFF_PBOX + (size_t)Bn*Nn*4)
#define OFF_TD    (OFF_VALID + (size_t)Bn*Nn)
#define OFF_GRADS (OFF_TD + (size_t)Bn*Nn*3)

#define NSLICE 4   // b-slices for the grads reduction

// Scratch (__device__ globals)
__device__ int4   g_boxi[Bn*Nn];            // {yp, xp, ph, pw}; 0 if invalid
__device__ float4 g_boxf[Bn*Nn];            // {inv_y, yp*inv_y+0.5, inv_x, xp*inv_x+0.5}
__device__ float  g_A[Bn*Nn*PH];            // row weight sums per box
__device__ float  g_Bw[Bn*Nn*PW];           // col weight sums per box
__device__ float  g_S[(size_t)Bn*NCELL];    // per-image rank-16 weight field (5.76 MB)
__device__ float  g_P[(size_t)NSLICE*NCELL*3]; // partial grads per slice (4.32 MB)

// ---------------------------------------------------------------------------
// Kernel 1: fused _create + separable VJP vectors. One block per (b,n).
// ---------------------------------------------------------------------------
__global__ void __launch_bounds__(320) k_init(const float* __restrict__ boxes,
                                              const int*   __restrict__ td,
                                              float* __restrict__ out)
{
    const int bn = blockIdx.x;

    float ymin = __ldg(boxes + bn*4+0);
    float xmin = __ldg(boxes + bn*4+1);
    float ymax = __ldg(boxes + bn*4+2);
    float xmax = __ldg(boxes + bn*4+3);

    float h  = ymax - ymin;
    float w  = xmax - xmin;
    float pwf = h * 0.5f;
    float phf = pwf;
    float oy = ymin + h * 0.5f;
    float ox = xmin + w * 0.5f;
    float yp = fmaxf(oy - phf * 0.5f, 0.0f);
    float xp = fmaxf(ox - pwf * 0.5f, 0.0f);
    if (yp + phf > (float)Hh) yp = (float)Hh - phf;
    if (xp + pwf > (float)Ww) xp = (float)Ww - pwf;

    bool valid = (phf > MINPH);

    int4 bi; float4 bf;
    if (!valid) {
        bi = make_int4(0,0,0,0);
        bf = make_float4(0.f,0.f,0.f,0.f);
    } else {
        int ypi = (int)yp, xpi = (int)xp;
        int phi = max((int)phf, 1);
        int pwi = max((int)pwf, 1);
        bi = make_int4(ypi, xpi, phi, pwi);
        float s0 = (float)phi / (float)PH;  float inv0 = 1.0f / s0;
        float s1 = (float)pwi / (float)PW;  float inv1 = 1.0f / s1;
        bf = make_float4(inv0, (float)ypi*inv0 + 0.5f,
                         inv1, (float)xpi*inv1 + 0.5f);
    }

    if (threadIdx.x == 0) {
        float* out_pb = out + OFF_PBOX;
        out_pb[bn*4+0] = yp; out_pb[bn*4+1] = xp;
        out_pb[bn*4+2] = phf; out_pb[bn*4+3] = pwf;
        out[OFF_VALID + bn] = valid ? 1.0f : 0.0f;
        #pragma unroll
        for (int k = 0; k < 3; ++k)
            out[OFF_TD + (size_t)bn*3 + k] = (__ldg(td + bn*3+k) != 0) ? 1.0f : 0.0f;
        g_boxi[bn] = bi;
        g_boxf[bn] = bf;
    }

    int p = threadIdx.x;
    if (p >= PH) return;
    float a = 0.0f, bb = 0.0f;
    if (bi.z > 0) {
        {
            float r = (float)bi.z / (float)PH;
            int k0 = (int)floorf(((float)p + 0.5f) * r - 0.5f) - 2;
            #pragma unroll
            for (int dk = 0; dk < 5; ++dk) {
                int k = k0 + dk;
                if (k < 0 || k >= bi.z) continue;
                float u = ((float)k + 0.5f) * bf.x - 0.5f;
                float wgt = 1.0f - fabsf(u - (float)p);
                if (wgt > 0.0f) a += wgt;
            }
        }
        {
            float r = (float)bi.w / (float)PW;
            int k0 = (int)floorf(((float)p + 0.5f) * r - 0.5f) - 2;
            #pragma unroll
            for (int dk = 0; dk < 5; ++dk) {
                int k = k0 + dk;
                if (k < 0 || k >= bi.w) continue;
                float u = ((float)k + 0.5f) * bf.z - 0.5f;
                float wgt = 1.0f - fabsf(u - (float)p);
                if (wgt > 0.0f) bb += wgt;
            }
        }
    }
    g_A [bn*PH + p] = a;
    g_Bw[bn*PW + p] = bb;
}

// ---------------------------------------------------------------------------
// Bilinear sample of patch (3 channels) at image pixel (fi, jj) under box f.
// ---------------------------------------------------------------------------
__device__ __forceinline__ void bil3(float4 f, float fi, int jj,
                                     const float* __restrict__ patch, float* o)
{
    float u  = fi * f.x - f.y;
    float vv = ((float)jj + 0.5f) * f.z - f.w;
    float fu = floorf(u), fv = floorf(vv);
    float du = u - fu,    dv = vv - fv;
    int r0 = (int)fu, c0 = (int)fv;
    const float* p00 = patch + ((size_t)r0 * PW + c0) * 3;
    float w00 = (1.0f-du)*(1.0f-dv);
    float w01 = (1.0f-du)*dv;
    float w10 = du*(1.0f-dv);
    float w11 = du*dv;
    #pragma unroll
    for (int c = 0; c < 3; ++c)
        o[c] = w00*p00[c] + w01*p00[3+c] + w10*p00[PW*3+c] + w11*p00[PW*3+3+c];
}

// ---------------------------------------------------------------------------
// Kernel 2: image composite (exact R4 form — proven fastest variant).
// ---------------------------------------------------------------------------
__global__ void __launch_bounds__(256) k_image(const float* __restrict__ images,
                                               const float* __restrict__ patch,
                                               float* __restrict__ out)
{
    const int b    = blockIdx.z;
    const int j0   = blockIdx.x * 128;
    const int i    = blockIdx.y * 8 + (threadIdx.x >> 5);
    const int lane = threadIdx.x & 31;

    __shared__ int4   sbi[Nn];
    __shared__ float4 sbf[Nn];
    if (threadIdx.x < Nn) {
        sbi[threadIdx.x] = g_boxi[b*Nn + threadIdx.x];
        sbf[threadIdx.x] = g_boxf[b*Nn + threadIdx.x];
    }
    __syncthreads();

    bool inter = false;
    if (lane < Nn) {
        int4 bx = sbi[lane];
        inter = (bx.z > 0) &&
                ((unsigned)(i - bx.x) < (unsigned)bx.z) &&
                (bx.y < j0 + 128) && (bx.y + bx.w > j0);
    }
    unsigned mask = __ballot_sync(0xffffffffu, inter);

    size_t fbase = ((size_t)b * NPIX + (size_t)i * Ww + j0) * 3;
    const float4* src4 = (const float4*)(images + fbase);
    float4*       dst4 = (float4*)(out + fbase);

    if (mask == 0u) {
        dst4[lane     ] = src4[lane     ];
        dst4[lane + 32] = src4[lane + 32];
        dst4[lane + 64] = src4[lane + 64];
        return;
    }

    const float fi = (float)i + 0.5f;

    #pragma unroll
    for (int r = 0; r < 3; ++r) {
        int l4 = lane + r*32;
        int f0 = l4 * 4;
        int pa = f0 / 3;
        int pb = (f0 + 3) / 3;

        int hitA = -1, hitB = -1;
        {
            int ja = j0 + pa, jb = j0 + pb;
            unsigned m = mask;
            while (m) {
                int n = 31 - __clz(m);
                int4 bx = sbi[n];
                if (hitA < 0 && (unsigned)(ja - bx.y) < (unsigned)bx.w) hitA = n;
                if (hitB < 0 && (unsigned)(jb - bx.y) < (unsigned)bx.w) hitB = n;
                if (hitA >= 0 && hitB >= 0) break;
                m &= ~(1u << n);
            }
        }

        float va[3], vb[3];
        if (hitA >= 0) bil3(sbf[hitA], fi, j0 + pa, patch, va);
        if (hitB >= 0) bil3(sbf[hitB], fi, j0 + pb, patch, vb);

        float4 v = make_float4(0.f, 0.f, 0.f, 0.f);
        if (hitA < 0 || hitB < 0)
            v = src4[l4];

        float ov[4] = { v.x, v.y, v.z, v.w };
        #pragma unroll
        for (int e = 0; e < 4; ++e) {
            int fidx = f0 + e;
            int p = fidx / 3;
            int c = fidx - p * 3;
            if (p == pa) { if (hitA >= 0) ov[e] = va[c]; }
            else         { if (hitB >= 0) ov[e] = vb[c]; }
        }
        dst4[l4] = make_float4(ov[0], ov[1], ov[2], ov[3]);
    }
}

// ---------------------------------------------------------------------------
// Kernel 3: S[b][p][q] = sum_n A_bn[p] * B_bn[q]  (rank-16 outer product)
// ---------------------------------------------------------------------------
#define PCHUNK 30
__global__ void __launch_bounds__(320) k_s()
{
    const int b  = blockIdx.y;
    const int p0 = blockIdx.x * PCHUNK;
    const int q  = threadIdx.x;

    __shared__ float As[Nn][PH];
    for (int idx = threadIdx.x; idx < Nn*PH; idx += 320) {
        int n = idx / PH, p = idx - n * PH;
        As[n][p] = g_A[(b*Nn + n)*PH + p];
    }
    __syncthreads();
    if (q >= PW) return;

    float Br[Nn];
    #pragma unroll
    for (int n = 0; n < Nn; ++n)
        Br[n] = g_Bw[(b*Nn + n)*PW + q];

    #pragma unroll
    for (int dp = 0; dp < PCHUNK; ++dp) {
        int p = p0 + dp;
        float s = 0.0f;
        #pragma unroll
        for (int n = 0; n < Nn; ++n)
            s += As[n][p] * Br[n];
        g_S[((size_t)b*PH + p)*PW + q] = s;
    }
}

// ---------------------------------------------------------------------------
// Kernel 4: partial grads per b-slice (4 images each). float4 loads, 352 blocks.
// ---------------------------------------------------------------------------
__global__ void __launch_bounds__(256) k_g1(const float* __restrict__ hg)
{
    const int slice = blockIdx.y;
    const int t     = blockIdx.x * 256 + threadIdx.x;
    const int cell0 = t * 4;
    if (cell0 >= NCELL) return;

    float o[12];
    #pragma unroll
    for (int j = 0; j < 12; ++j) o[j] = 0.0f;

    #pragma unroll
    for (int k = 0; k < Bn/NSLICE; ++k) {
        const int b = slice * (Bn/NSLICE) + k;
        const float4 s4 = *(const float4*)(g_S + (size_t)b*NCELL + cell0);
        const float4* h4 = (const float4*)(hg + ((size_t)b*NCELL + cell0)*3);
        float4 h0 = h4[0];
        float4 h1 = h4[1];
        float4 h2 = h4[2];
        float s[4]   = { s4.x, s4.y, s4.z, s4.w };
        float hh[12] = { h0.x,h0.y,h0.z,h0.w, h1.x,h1.y,h1.z,h1.w,
                         h2.x,h2.y,h2.z,h2.w };
        #pragma unroll
        for (int j = 0; j < 12; ++j)
            o[j] += s[j/3] * hh[j];
    }

    float4* p4 = (float4*)(g_P + ((size_t)slice*NCELL + cell0)*3);
    p4[0] = make_float4(o[0], o[1], o[2],  o[3]);
    p4[1] = make_float4(o[4], o[5], o[6],  o[7]);
    p4[2] = make_float4(o[8], o[9], o[10], o[11]);
}

// ---------------------------------------------------------------------------
// Kernel 5: reduce the NSLICE partials into grads output.
// ---------------------------------------------------------------------------
__global__ void __launch_bounds__(256) k_g2(float* __restrict__ outg)
{
    const int t = blockIdx.x * 256 + threadIdx.x;     // float4 index
    if (t >= NCELL*3/4) return;

    float4 acc = make_float4(0.f, 0.f, 0.f, 0.f);
    #pragma unroll
    for (int s = 0; s < NSLICE; ++s) {
        float4 v = *(const float4*)(g_P + (size_t)s*NCELL*3 + t*4);
        acc.x += v.x; acc.y += v.y; acc.z += v.z; acc.w += v.w;
    }
    ((float4*)outg)[t] = acc;
}

// ---------------------------------------------------------------------------
extern "C" void kernel_launch(void* const* d_in, const int* in_sizes, int n_in,
                              void* d_out, int out_size)
{
    const float* boxes  = (const float*)d_in[0];
    const float* images = (const float*)d_in[1];
    const float* patch  = (const float*)d_in[2];
    const float* hg     = (const float*)d_in[3];
    const int*   td     = (const int*)  d_in[4];
    float* out = (float*)d_out;

    k_init<<<Bn*Nn, 320>>>(boxes, td, out);
    k_s<<<dim3(PH/PCHUNK, Bn), 320>>>();
    k_image<<<dim3(Ww/128, Hh/8, Bn), 256>>>(images, patch, out);
    k_g1<<<dim3((NCELL/4 + 255)/256, NSLICE), 256>>>(hg);
    k_g2<<<(NCELL*3/4 + 255)/256, 256>>>(out + OFF_GRADS);
}